// round 6
// baseline (speedup 1.0000x reference)
#include <cuda_runtime.h>
#include <cuda_bf16.h>
#include <cstdint>

// ---------------------------------------------------------------------------
// Problem constants
// ---------------------------------------------------------------------------
#define DD    101                 // inner dim (x cols)
#define KO    101                 // output cols
#define BM    64                  // batch rows per tile
#define NTHR  256
#define NROWS 104                 // A rows padded (13*8)
#define ASTR  240                 // A smem row stride bytes (120 bf16)
#define A_IMG_BYTES (NROWS * ASTR)        // 24960 per hi/lo

#define TILE_BYTES (BM * DD * 4)          // 25856
#define RAW_SLOT   26112                  // tile + 256 zeroed pad

// smem layout (bytes)
#define RAW0_OFF 0
#define RAW1_OFF RAW_SLOT                 // 26112
#define AH_OFF   (2 * RAW_SLOT)           // 52224
#define AL_OFF   (AH_OFF + A_IMG_BYTES)   // 77184
#define MBAR_OFF (AH_OFF + 2 * A_IMG_BYTES)  // 102144
#define SMEM_BYTES 102400

#define GRID 296                          // 2 CTAs/SM

__device__ __align__(16) unsigned char g_Aimg[2 * A_IMG_BYTES];

// ---------------------------------------------------------------------------
// Helpers
// ---------------------------------------------------------------------------
__device__ __forceinline__ uint32_t smem_u32(const void* p) {
    uint32_t a;
    asm("{ .reg .u64 t; cvta.to.shared.u64 t, %1; cvt.u32.u64 %0, t; }"
        : "=r"(a) : "l"(p));
    return a;
}
__device__ __forceinline__ void mbar_init(uint32_t m, uint32_t cnt) {
    asm volatile("mbarrier.init.shared.b64 [%0], %1;" :: "r"(m), "r"(cnt) : "memory");
}
__device__ __forceinline__ void mbar_expect_tx(uint32_t m, uint32_t bytes) {
    asm volatile("mbarrier.arrive.expect_tx.shared.b64 _, [%0], %1;"
                 :: "r"(m), "r"(bytes) : "memory");
}
__device__ __forceinline__ void mbar_wait(uint32_t m, uint32_t parity) {
    asm volatile(
        "{\n\t.reg .pred P;\n"
        "W_%=:\n\t"
        "mbarrier.try_wait.parity.acquire.cta.shared::cta.b64 P, [%0], %1;\n\t"
        "@!P bra W_%=;\n\t}"
        :: "r"(m), "r"(parity) : "memory");
}
__device__ __forceinline__ void bulk_g2s(uint32_t dst, const void* src,
                                         uint32_t bytes, uint32_t m) {
    asm volatile(
        "cp.async.bulk.shared::cta.global.mbarrier::complete_tx::bytes "
        "[%0], [%1], %2, [%3];"
        :: "r"(dst), "l"(src), "r"(bytes), "r"(m) : "memory");
}
__device__ __forceinline__ float ldsf(uint32_t a) {
    float v;
    asm volatile("ld.shared.f32 %0, [%1];" : "=f"(v) : "r"(a));
    return v;
}
__device__ __forceinline__ void ldsm_x4(uint32_t* r, uint32_t addr) {
    asm volatile("ldmatrix.sync.aligned.m8n8.x4.shared.b16 {%0,%1,%2,%3}, [%4];"
                 : "=r"(r[0]), "=r"(r[1]), "=r"(r[2]), "=r"(r[3]) : "r"(addr));
}
__device__ __forceinline__ void ldsm_x2(uint32_t* r, uint32_t addr) {
    asm volatile("ldmatrix.sync.aligned.m8n8.x2.shared.b16 {%0,%1}, [%2];"
                 : "=r"(r[0]), "=r"(r[1]) : "r"(addr));
}
__device__ __forceinline__ void mma_bf16(float* c, const uint32_t* a,
                                         const uint32_t* b) {
    asm volatile(
        "mma.sync.aligned.m16n8k16.row.col.f32.bf16.bf16.f32 "
        "{%0,%1,%2,%3}, {%4,%5,%6,%7}, {%8,%9}, {%0,%1,%2,%3};"
        : "+f"(c[0]), "+f"(c[1]), "+f"(c[2]), "+f"(c[3])
        : "r"(a[0]), "r"(a[1]), "r"(a[2]), "r"(a[3]), "r"(b[0]), "r"(b[1]));
}
__device__ __forceinline__ void split2(float f0, float f1,
                                       uint32_t& hi, uint32_t& lo) {
    asm("cvt.rn.bf16x2.f32 %0, %1, %2;" : "=r"(hi) : "f"(f1), "f"(f0));
    float l0 = f0 - __uint_as_float(hi << 16);
    float l1 = f1 - __uint_as_float(hi & 0xffff0000u);
    asm("cvt.rn.bf16x2.f32 %0, %1, %2;" : "=r"(lo) : "f"(l1), "f"(l0));
}

// ---------------------------------------------------------------------------
// Kernel 1: fold constants -> bf16 hi/lo operator image (zero-padded rows).
// ---------------------------------------------------------------------------
extern __shared__ float bsm[];
__global__ void build_A_kernel(const float* __restrict__ Wre,
                               const float* __restrict__ Wim,
                               const float* __restrict__ ReJ,
                               const float* __restrict__ ImJ) {
    float* sRe = bsm;
    float* sIm = bsm + 10201;
    float* sW  = bsm + 20402;          // [Wre row][Wim row]
    const int tid = threadIdx.x;       // 128
    const int n   = blockIdx.x;        // 0..103

    for (int i = tid; i < 10201; i += 128) { sRe[i] = ReJ[i]; sIm[i] = ImJ[i]; }
    for (int i = tid; i < DD; i += 128) {
        sW[i]      = (n < KO) ? Wre[n * DD + i] : 0.0f;
        sW[DD + i] = (n < KO) ? Wim[n * DD + i] : 0.0f;
    }
    __syncthreads();

    const int d = tid;
    if (d >= ASTR / 2) return;
    float a = 0.0f;
    if (n < KO && d < DD) {
        float a0 = 0.f, a1 = 0.f;
        #pragma unroll 1
        for (int m = 0; m + 2 <= DD; m += 2) {
            a0 = fmaf(sW[m],        sRe[m*DD+d],     a0);
            a0 = fmaf(-sW[DD+m],    sIm[m*DD+d],     a0);
            a1 = fmaf(sW[m+1],      sRe[(m+1)*DD+d], a1);
            a1 = fmaf(-sW[DD+m+1],  sIm[(m+1)*DD+d], a1);
        }
        a0 = fmaf(sW[DD-1],     sRe[(DD-1)*DD+d], a0);
        a0 = fmaf(-sW[2*DD-1],  sIm[(DD-1)*DD+d], a0);
        a = (a0 + a1) * (1.0f / 101.0f);
    }
    __nv_bfloat16 hi = __float2bfloat16(a);
    __nv_bfloat16 lo = __float2bfloat16(a - __bfloat162float(hi));
    *(__nv_bfloat16*)(g_Aimg + n * ASTR + d * 2)               = hi;
    *(__nv_bfloat16*)(g_Aimg + A_IMG_BYTES + n * ASTR + d * 2) = lo;
}

// ---------------------------------------------------------------------------
// Kernel 2: persistent GEMM; bulk-copied double-buffered tiles; kt loop is
// software-pipelined (prefetch kt+1 frags during kt MMAs).
// ---------------------------------------------------------------------------
extern __shared__ unsigned char smem[];

__global__ void __launch_bounds__(NTHR, 2)
fourier_mma_kernel(const float* __restrict__ x, float* __restrict__ out,
                   int ntiles) {
    const int tid   = threadIdx.x;
    const int wid   = tid >> 5;
    const int lane  = tid & 31;
    const int mwarp = wid >> 1;
    const int nhalf = wid & 1;
    const uint32_t sbase = smem_u32(smem);
    const uint32_t mb0 = sbase + MBAR_OFF;
    const uint32_t mb1 = sbase + MBAR_OFF + 8;

    for (int i = tid; i < (RAW_SLOT - TILE_BYTES) / 4; i += NTHR) {
        *(uint32_t*)(smem + RAW0_OFF + TILE_BYTES + i * 4) = 0;
        *(uint32_t*)(smem + RAW1_OFF + TILE_BYTES + i * 4) = 0;
    }
    if (tid == 0) { mbar_init(mb0, 1); mbar_init(mb1, 1); }
    __syncthreads();

    int t = blockIdx.x;
    if (tid == 0) {
        mbar_expect_tx(mb0, 2 * A_IMG_BYTES + TILE_BYTES);
        bulk_g2s(sbase + AH_OFF, g_Aimg, 2 * A_IMG_BYTES, mb0);
        bulk_g2s(sbase + RAW0_OFF, (const char*)x + (size_t)t * TILE_BYTES,
                 TILE_BYTES, mb0);
    }

    const uint32_t ra = (uint32_t)((mwarp * 16 + (lane >> 2)) * DD
                                   + (lane & 3) * 2) * 4u;
    const uint32_t bh = sbase + AH_OFF
        + (uint32_t)((nhalf * 56 + ((lane >> 4) * 8) + (lane & 7)) * ASTR
                     + ((lane >> 3) & 1) * 16);
    const uint32_t bl = bh + (AL_OFF - AH_OFF);
    const uint32_t b6h = sbase + AH_OFF
        + (uint32_t)((nhalf * 56 + 48 + (lane & 7)) * ASTR
                     + ((lane >> 3) & 1) * 16);
    const uint32_t b6l = b6h + (AL_OFF - AH_OFF);

    int buf = 0;
    uint32_t par0 = 0, par1 = 0;
    #pragma unroll 1
    for (; t < ntiles; t += GRID) {
        const int tn = t + GRID;
        if (tn < ntiles && tid == 0) {
            const uint32_t mb_nxt = buf ? mb0 : mb1;
            mbar_expect_tx(mb_nxt, TILE_BYTES);
            bulk_g2s(sbase + (buf ? RAW0_OFF : RAW1_OFF),
                     (const char*)x + (size_t)tn * TILE_BYTES, TILE_BYTES, mb_nxt);
        }
        if (buf) { mbar_wait(mb1, par1); par1 ^= 1; }
        else     { mbar_wait(mb0, par0); par0 ^= 1; }

        float acc[7][4];
        #pragma unroll
        for (int nt = 0; nt < 7; ++nt)
            #pragma unroll
            for (int i = 0; i < 4; ++i) acc[nt][i] = 0.0f;

        const uint32_t rb = sbase + (buf ? RAW1_OFF : RAW0_OFF) + ra;

        // ---- software-pipelined mainloop: ping-pong frag registers ----
        float    fr[2][8];
        uint32_t bHr[2][14], bLr[2][14];

        // preload kt = 0
        {
            const uint32_t ka = rb;
            fr[0][0] = ldsf(ka);          fr[0][1] = ldsf(ka + 4);
            fr[0][2] = ldsf(ka + 3232);   fr[0][3] = ldsf(ka + 3236);
            fr[0][4] = ldsf(ka + 32);     fr[0][5] = ldsf(ka + 36);
            fr[0][6] = ldsf(ka + 3264);   fr[0][7] = ldsf(ka + 3268);
            ldsm_x4(bHr[0] + 0, bh);
            ldsm_x4(bHr[0] + 4, bh + 16 * ASTR);
            ldsm_x4(bHr[0] + 8, bh + 32 * ASTR);
            ldsm_x4(bLr[0] + 0, bl);
            ldsm_x4(bLr[0] + 4, bl + 16 * ASTR);
            ldsm_x4(bLr[0] + 8, bl + 32 * ASTR);
            if (nhalf == 0) { ldsm_x2(bHr[0] + 12, b6h); ldsm_x2(bLr[0] + 12, b6l); }
        }

        #pragma unroll
        for (int kt = 0; kt < 7; ++kt) {
            const int cur = kt & 1, nxt = cur ^ 1;
            if (kt < 6) {   // prefetch kt+1 while kt computes
                const uint32_t ka = rb + (uint32_t)(kt + 1) * 64u;
                const uint32_t ko = (uint32_t)(kt + 1) * 32u;
                fr[nxt][0] = ldsf(ka);          fr[nxt][1] = ldsf(ka + 4);
                fr[nxt][2] = ldsf(ka + 3232);   fr[nxt][3] = ldsf(ka + 3236);
                fr[nxt][4] = ldsf(ka + 32);     fr[nxt][5] = ldsf(ka + 36);
                fr[nxt][6] = ldsf(ka + 3264);   fr[nxt][7] = ldsf(ka + 3268);
                ldsm_x4(bHr[nxt] + 0, bh + ko);
                ldsm_x4(bHr[nxt] + 4, bh + 16 * ASTR + ko);
                ldsm_x4(bHr[nxt] + 8, bh + 32 * ASTR + ko);
                ldsm_x4(bLr[nxt] + 0, bl + ko);
                ldsm_x4(bLr[nxt] + 4, bl + 16 * ASTR + ko);
                ldsm_x4(bLr[nxt] + 8, bl + 32 * ASTR + ko);
                if (nhalf == 0) {
                    ldsm_x2(bHr[nxt] + 12, b6h + ko);
                    ldsm_x2(bLr[nxt] + 12, b6l + ko);
                }
            }

            uint32_t aH[4], aL[4];
            split2(fr[cur][0], fr[cur][1], aH[0], aL[0]);
            split2(fr[cur][2], fr[cur][3], aH[1], aL[1]);
            split2(fr[cur][4], fr[cur][5], aH[2], aL[2]);
            split2(fr[cur][6], fr[cur][7], aH[3], aL[3]);

            const uint32_t* bH = bHr[cur];
            const uint32_t* bL = bLr[cur];
            #pragma unroll
            for (int nt = 0; nt < 6; ++nt) mma_bf16(acc[nt], aH, bH + 2*nt);
            if (nhalf == 0)                mma_bf16(acc[6], aH, bH + 12);
            #pragma unroll
            for (int nt = 0; nt < 6; ++nt) mma_bf16(acc[nt], aH, bL + 2*nt);
            if (nhalf == 0)                mma_bf16(acc[6], aH, bL + 12);
            #pragma unroll
            for (int nt = 0; nt < 6; ++nt) mma_bf16(acc[nt], aL, bH + 2*nt);
            if (nhalf == 0)                mma_bf16(acc[6], aL, bH + 12);
        }

        // ---- epilogue: direct stores ----
        {
            const size_t ob = (size_t)t * BM * KO;
            const int r0 = mwarp * 16 + (lane >> 2);
            #pragma unroll
            for (int nt = 0; nt < 7; ++nt) {
                const int col = nhalf * 56 + nt * 8 + (lane & 3) * 2;
                if (col < KO) {
                    out[ob + (size_t)r0 * KO + col]       = acc[nt][0];
                    out[ob + (size_t)(r0 + 8) * KO + col] = acc[nt][2];
                    if (col + 1 < KO) {
                        out[ob + (size_t)r0 * KO + col + 1]       = acc[nt][1];
                        out[ob + (size_t)(r0 + 8) * KO + col + 1] = acc[nt][3];
                    }
                }
            }
        }
        __syncthreads();
        buf ^= 1;
    }
}

// ---------------------------------------------------------------------------
// Launch
// ---------------------------------------------------------------------------
extern "C" void kernel_launch(void* const* d_in, const int* in_sizes, int n_in,
                              void* d_out, int out_size) {
    const float* x   = (const float*)d_in[0];
    const float* Wre = (const float*)d_in[1];
    const float* Wim = (const float*)d_in[2];
    const float* ReJ = (const float*)d_in[3];
    const float* ImJ = (const float*)d_in[4];
    float* out = (float*)d_out;

    const int B = in_sizes[0] / DD;
    const int ntiles = B / BM;

    const int build_smem = (20402 + 2 * DD) * (int)sizeof(float);
    cudaFuncSetAttribute(build_A_kernel,
                         cudaFuncAttributeMaxDynamicSharedMemorySize, build_smem);
    build_A_kernel<<<NROWS, 128, build_smem>>>(Wre, Wim, ReJ, ImJ);

    cudaFuncSetAttribute(fourier_mma_kernel,
                         cudaFuncAttributeMaxDynamicSharedMemorySize, SMEM_BYTES);
    fourier_mma_kernel<<<GRID, NTHR, SMEM_BYTES>>>(x, out, ntiles);
    (void)n_in; (void)out_size;
}

// round 7
// speedup vs baseline: 1.0804x; 1.0804x over previous
#include <cuda_runtime.h>
#include <cuda_bf16.h>
#include <cstdint>

// ---------------------------------------------------------------------------
// Problem constants
// ---------------------------------------------------------------------------
#define DD    101                 // inner dim
#define KO    101                 // output cols
#define KPAD  104                 // 13 * 8
#define BM    64                  // batch rows per tile
#define NTHR  256

#define ASTRW 104                 // A image row stride (words) = n width
#define A_IMG_BYTES (KPAD * ASTRW * 4)    // 43264

#define TILE_BYTES (BM * DD * 4)          // 25856
#define RAW_SLOT   26112                  // tile + 256 zeroed pad

// smem layout (bytes)
#define RAW0_OFF 0
#define RAW1_OFF RAW_SLOT                 // 26112
#define AIMG_OFF (2 * RAW_SLOT)           // 52224
#define MBAR_OFF (AIMG_OFF + A_IMG_BYTES) // 95488
#define SMEM_BYTES 95552

#define GRID 296                          // 2 CTAs/SM

// Combined operator, tf32-rounded fp32 bits, [k=d][n=kout] layout, zero-padded.
__device__ __align__(16) uint32_t g_Atf[KPAD * ASTRW];

// ---------------------------------------------------------------------------
// Helpers
// ---------------------------------------------------------------------------
__device__ __forceinline__ uint32_t smem_u32(const void* p) {
    uint32_t a;
    asm("{ .reg .u64 t; cvta.to.shared.u64 t, %1; cvt.u32.u64 %0, t; }"
        : "=r"(a) : "l"(p));
    return a;
}
__device__ __forceinline__ void mbar_init(uint32_t m, uint32_t cnt) {
    asm volatile("mbarrier.init.shared.b64 [%0], %1;" :: "r"(m), "r"(cnt) : "memory");
}
__device__ __forceinline__ void mbar_expect_tx(uint32_t m, uint32_t bytes) {
    asm volatile("mbarrier.arrive.expect_tx.shared.b64 _, [%0], %1;"
                 :: "r"(m), "r"(bytes) : "memory");
}
__device__ __forceinline__ void mbar_wait(uint32_t m, uint32_t parity) {
    asm volatile(
        "{\n\t.reg .pred P;\n"
        "W_%=:\n\t"
        "mbarrier.try_wait.parity.acquire.cta.shared::cta.b64 P, [%0], %1;\n\t"
        "@!P bra W_%=;\n\t}"
        :: "r"(m), "r"(parity) : "memory");
}
__device__ __forceinline__ void bulk_g2s(uint32_t dst, const void* src,
                                         uint32_t bytes, uint32_t m) {
    asm volatile(
        "cp.async.bulk.shared::cta.global.mbarrier::complete_tx::bytes "
        "[%0], [%1], %2, [%3];"
        :: "r"(dst), "l"(src), "r"(bytes), "r"(m) : "memory");
}
__device__ __forceinline__ float ldsf(uint32_t a) {
    float v;
    asm volatile("ld.shared.f32 %0, [%1];" : "=f"(v) : "r"(a));
    return v;
}
__device__ __forceinline__ uint32_t ldsu(uint32_t a) {
    uint32_t v;
    asm volatile("ld.shared.b32 %0, [%1];" : "=r"(v) : "r"(a));
    return v;
}
__device__ __forceinline__ uint32_t to_tf32(float f) {
    uint32_t r;
    asm("cvt.rna.tf32.f32 %0, %1;" : "=r"(r) : "f"(f));
    return r;
}
__device__ __forceinline__ void mma_tf32(float* c, const uint32_t* a,
                                         const uint32_t* b) {
    asm volatile(
        "mma.sync.aligned.m16n8k8.row.col.f32.tf32.tf32.f32 "
        "{%0,%1,%2,%3}, {%4,%5,%6,%7}, {%8,%9}, {%0,%1,%2,%3};"
        : "+f"(c[0]), "+f"(c[1]), "+f"(c[2]), "+f"(c[3])
        : "r"(a[0]), "r"(a[1]), "r"(a[2]), "r"(a[3]), "r"(b[0]), "r"(b[1]));
}

// ---------------------------------------------------------------------------
// Kernel 1: fold constants -> combined operator -> tf32 image [d][n] (transposed,
// zero-padded). A_op[n,d] = ( sum_m Wre[n,m]*ReJ[m,d] - Wim[n,m]*ImJ[m,d] ) / 101
// ---------------------------------------------------------------------------
extern __shared__ float bsm[];
__global__ void build_A_kernel(const float* __restrict__ Wre,
                               const float* __restrict__ Wim,
                               const float* __restrict__ ReJ,
                               const float* __restrict__ ImJ) {
    float* sRe = bsm;
    float* sIm = bsm + 10201;
    float* sW  = bsm + 20402;          // [Wre row][Wim row]
    const int tid = threadIdx.x;       // 128
    const int n   = blockIdx.x;        // 0..103 (output row of A_op)

    for (int i = tid; i < 10201; i += 128) { sRe[i] = ReJ[i]; sIm[i] = ImJ[i]; }
    for (int i = tid; i < DD; i += 128) {
        sW[i]      = (n < KO) ? Wre[n * DD + i] : 0.0f;
        sW[DD + i] = (n < KO) ? Wim[n * DD + i] : 0.0f;
    }
    __syncthreads();

    const int d = tid;
    if (d >= KPAD) return;
    float a = 0.0f;
    if (n < KO && d < DD) {
        float a0 = 0.f, a1 = 0.f;
        #pragma unroll 1
        for (int m = 0; m + 2 <= DD; m += 2) {
            a0 = fmaf(sW[m],        sRe[m*DD+d],     a0);
            a0 = fmaf(-sW[DD+m],    sIm[m*DD+d],     a0);
            a1 = fmaf(sW[m+1],      sRe[(m+1)*DD+d], a1);
            a1 = fmaf(-sW[DD+m+1],  sIm[(m+1)*DD+d], a1);
        }
        a0 = fmaf(sW[DD-1],     sRe[(DD-1)*DD+d], a0);
        a0 = fmaf(-sW[2*DD-1],  sIm[(DD-1)*DD+d], a0);
        a = (a0 + a1) * (1.0f / 101.0f);
    }
    g_Atf[d * ASTRW + n] = to_tf32(a);   // transposed store, tf32-rounded
}

// ---------------------------------------------------------------------------
// Kernel 2: persistent GEMM, single-pass tf32 m16n8k8.
//   out[b, n] = sum_d x[b, d] * Aimg[d][n]
// Warp layout: mwarp = wid>>1 -> rows [mwarp*16,+16); nhalf = wid&1 ->
//   cols [0,56) (7 n-tiles) or [56,104) (6 n-tiles).
// ---------------------------------------------------------------------------
extern __shared__ unsigned char smem[];

__global__ void __launch_bounds__(NTHR, 2)
fourier_mma_kernel(const float* __restrict__ x, float* __restrict__ out,
                   int ntiles) {
    const int tid   = threadIdx.x;
    const int wid   = tid >> 5;
    const int lane  = tid & 31;
    const int g     = lane >> 2;      // groupID (row within frag)
    const int tg    = lane & 3;       // threadID in group (k / col selector)
    const int mwarp = wid >> 1;
    const int nhalf = wid & 1;
    const int NT    = nhalf ? 6 : 7;  // n-tiles this warp owns
    const uint32_t sbase = smem_u32(smem);
    const uint32_t mb0 = sbase + MBAR_OFF;
    const uint32_t mb1 = sbase + MBAR_OFF + 8;

    // zero raw-slot pad tails (K-tail overreads must be finite; x0 against A pad)
    for (int i = tid; i < (RAW_SLOT - TILE_BYTES) / 4; i += NTHR) {
        *(uint32_t*)(smem + RAW0_OFF + TILE_BYTES + i * 4) = 0;
        *(uint32_t*)(smem + RAW1_OFF + TILE_BYTES + i * 4) = 0;
    }
    if (tid == 0) { mbar_init(mb0, 1); mbar_init(mb1, 1); }
    __syncthreads();

    int t = blockIdx.x;
    if (tid == 0) {      // prologue: A image + first tile
        mbar_expect_tx(mb0, A_IMG_BYTES + TILE_BYTES);
        bulk_g2s(sbase + AIMG_OFF, g_Atf, A_IMG_BYTES, mb0);
        bulk_g2s(sbase + RAW0_OFF, (const char*)x + (size_t)t * TILE_BYTES,
                 TILE_BYTES, mb0);
    }

    // a-frag base: row = mwarp*16 + g, col word = tg  (bytes)
    const uint32_t ra = (uint32_t)((mwarp * 16 + g) * DD + tg) * 4u;
    // b-frag base: k-row = tg, n-col = nhalf*56 + g  (bytes)
    const uint32_t rbA = sbase + AIMG_OFF
        + (uint32_t)(tg * ASTRW + nhalf * 56 + g) * 4u;

    int buf = 0;
    uint32_t par0 = 0, par1 = 0;
    #pragma unroll 1
    for (; t < ntiles; t += GRID) {
        const int tn = t + GRID;
        if (tn < ntiles && tid == 0) {
            const uint32_t mb_nxt = buf ? mb0 : mb1;
            mbar_expect_tx(mb_nxt, TILE_BYTES);
            bulk_g2s(sbase + (buf ? RAW0_OFF : RAW1_OFF),
                     (const char*)x + (size_t)tn * TILE_BYTES, TILE_BYTES, mb_nxt);
        }
        if (buf) { mbar_wait(mb1, par1); par1 ^= 1; }
        else     { mbar_wait(mb0, par0); par0 ^= 1; }

        float acc[7][4];
        #pragma unroll
        for (int nt = 0; nt < 7; ++nt)
            #pragma unroll
            for (int i = 0; i < 4; ++i) acc[nt][i] = 0.0f;

        const uint32_t rx = sbase + (buf ? RAW1_OFF : RAW0_OFF) + ra;

        #pragma unroll
        for (int kt = 0; kt < 13; ++kt) {
            // ---- a-frag: x rows (r, r+8), k cols (k0+tg, k0+tg+4) ----
            const uint32_t ka = rx + (uint32_t)kt * 32u;
            float f0 = ldsf(ka);                 // [g][tg]
            float f1 = ldsf(ka + 3232);          // [g+8][tg]   (8*101*4)
            float f2 = ldsf(ka + 16);            // [g][tg+4]
            float f3 = ldsf(ka + 3232 + 16);     // [g+8][tg+4]
            uint32_t a[4];
            a[0] = to_tf32(f0); a[1] = to_tf32(f1);
            a[2] = to_tf32(f2); a[3] = to_tf32(f3);

            // ---- b-frags: Aimg[k0+tg][n], Aimg[k0+tg+4][n] ----
            const uint32_t kb = rbA + (uint32_t)kt * (8u * ASTRW * 4u);
            uint32_t b[7][2];
            #pragma unroll
            for (int nt = 0; nt < 7; ++nt) {
                if (nt < NT) {
                    b[nt][0] = ldsu(kb + (uint32_t)nt * 32u);
                    b[nt][1] = ldsu(kb + (uint32_t)nt * 32u + 4u * ASTRW * 4u);
                }
            }
            #pragma unroll
            for (int nt = 0; nt < 7; ++nt)
                if (nt < NT) mma_tf32(acc[nt], a, b[nt]);
        }

        // ---- epilogue: direct stores ----
        {
            const size_t ob = (size_t)t * BM * KO;
            const int r0 = mwarp * 16 + g;
            #pragma unroll
            for (int nt = 0; nt < 7; ++nt) {
                if (nt >= NT) break;
                const int col = nhalf * 56 + nt * 8 + tg * 2;
                if (col < KO) {
                    out[ob + (size_t)r0 * KO + col]       = acc[nt][0];
                    out[ob + (size_t)(r0 + 8) * KO + col] = acc[nt][2];
                    if (col + 1 < KO) {
                        out[ob + (size_t)r0 * KO + col + 1]       = acc[nt][1];
                        out[ob + (size_t)(r0 + 8) * KO + col + 1] = acc[nt][3];
                    }
                }
            }
        }
        __syncthreads();      // all warps done with raw[buf] before refill
        buf ^= 1;
    }
}

// ---------------------------------------------------------------------------
// Launch
// ---------------------------------------------------------------------------
extern "C" void kernel_launch(void* const* d_in, const int* in_sizes, int n_in,
                              void* d_out, int out_size) {
    const float* x   = (const float*)d_in[0];
    const float* Wre = (const float*)d_in[1];
    const float* Wim = (const float*)d_in[2];
    const float* ReJ = (const float*)d_in[3];
    const float* ImJ = (const float*)d_in[4];
    float* out = (float*)d_out;

    const int B = in_sizes[0] / DD;       // 262144
    const int ntiles = B / BM;            // 4096

    const int build_smem = (20402 + 2 * DD) * (int)sizeof(float);
    cudaFuncSetAttribute(build_A_kernel,
                         cudaFuncAttributeMaxDynamicSharedMemorySize, build_smem);
    build_A_kernel<<<KPAD, 128, build_smem>>>(Wre, Wim, ReJ, ImJ);

    cudaFuncSetAttribute(fourier_mma_kernel,
                         cudaFuncAttributeMaxDynamicSharedMemorySize, SMEM_BYTES);
    fourier_mma_kernel<<<GRID, NTHR, SMEM_BYTES>>>(x, out, ntiles);
    (void)n_in; (void)out_size;
}

// round 8
// speedup vs baseline: 1.5322x; 1.4182x over previous
#include <cuda_runtime.h>
#include <cuda_bf16.h>
#include <cstdint>

// ---------------------------------------------------------------------------
// Problem constants
// ---------------------------------------------------------------------------
#define DD    101                 // inner dim
#define KO    101                 // output cols
#define KPAD  104                 // 13 * 8
#define BM    64                  // batch rows per tile
#define NTHR  256

// B image: [kt][n][tg] float2 pairs = (A[k0+tg][n], A[k0+tg+4][n])
#define A_IMG_BYTES (13 * KPAD * 4 * 8)   // 43264

#define TILE_BYTES (BM * DD * 4)          // 25856
#define RAW_SLOT   26112                  // tile + 256 zeroed pad

// smem layout (bytes)
#define RAW0_OFF 0
#define RAW1_OFF RAW_SLOT                 // 26112
#define AIMG_OFF (2 * RAW_SLOT)           // 52224
#define MBAR_OFF (AIMG_OFF + A_IMG_BYTES) // 95488
#define SMEM_BYTES 95552

#define GRID 296                          // 2 CTAs/SM

__device__ __align__(16) unsigned char g_Apair[A_IMG_BYTES];

// ---------------------------------------------------------------------------
// Helpers
// ---------------------------------------------------------------------------
__device__ __forceinline__ uint32_t smem_u32(const void* p) {
    uint32_t a;
    asm("{ .reg .u64 t; cvta.to.shared.u64 t, %1; cvt.u32.u64 %0, t; }"
        : "=r"(a) : "l"(p));
    return a;
}
__device__ __forceinline__ void mbar_init(uint32_t m, uint32_t cnt) {
    asm volatile("mbarrier.init.shared.b64 [%0], %1;" :: "r"(m), "r"(cnt) : "memory");
}
__device__ __forceinline__ void mbar_expect_tx(uint32_t m, uint32_t bytes) {
    asm volatile("mbarrier.arrive.expect_tx.shared.b64 _, [%0], %1;"
                 :: "r"(m), "r"(bytes) : "memory");
}
__device__ __forceinline__ void mbar_wait(uint32_t m, uint32_t parity) {
    asm volatile(
        "{\n\t.reg .pred P;\n"
        "W_%=:\n\t"
        "mbarrier.try_wait.parity.acquire.cta.shared::cta.b64 P, [%0], %1;\n\t"
        "@!P bra W_%=;\n\t}"
        :: "r"(m), "r"(parity) : "memory");
}
__device__ __forceinline__ void bulk_g2s(uint32_t dst, const void* src,
                                         uint32_t bytes, uint32_t m) {
    asm volatile(
        "cp.async.bulk.shared::cta.global.mbarrier::complete_tx::bytes "
        "[%0], [%1], %2, [%3];"
        :: "r"(dst), "l"(src), "r"(bytes), "r"(m) : "memory");
}
__device__ __forceinline__ void bulk_s2g(void* gdst, uint32_t ssrc, uint32_t bytes) {
    asm volatile("cp.async.bulk.global.shared::cta.bulk_group [%0], [%1], %2;"
                 :: "l"(gdst), "r"(ssrc), "r"(bytes) : "memory");
}
#define S2G_COMMIT() asm volatile("cp.async.bulk.commit_group;" ::: "memory")
#define S2G_WAIT0()  asm volatile("cp.async.bulk.wait_group 0;" ::: "memory")

__device__ __forceinline__ float ldsf(uint32_t a) {
    float v;
    asm volatile("ld.shared.f32 %0, [%1];" : "=f"(v) : "r"(a));
    return v;
}
__device__ __forceinline__ void ldsv2(uint32_t* r, uint32_t a) {
    asm volatile("ld.shared.v2.b32 {%0,%1}, [%2];"
                 : "=r"(r[0]), "=r"(r[1]) : "r"(a));
}
__device__ __forceinline__ void stsf(uint32_t a, float v) {
    asm volatile("st.shared.f32 [%0], %1;" :: "r"(a), "f"(v) : "memory");
}
__device__ __forceinline__ uint32_t to_tf32(float f) {
    uint32_t r;
    asm("cvt.rna.tf32.f32 %0, %1;" : "=r"(r) : "f"(f));
    return r;
}
__device__ __forceinline__ void mma_tf32(float* c, const uint32_t* a,
                                         const uint32_t* b) {
    asm volatile(
        "mma.sync.aligned.m16n8k8.row.col.f32.tf32.tf32.f32 "
        "{%0,%1,%2,%3}, {%4,%5,%6,%7}, {%8,%9}, {%0,%1,%2,%3};"
        : "+f"(c[0]), "+f"(c[1]), "+f"(c[2]), "+f"(c[3])
        : "r"(a[0]), "r"(a[1]), "r"(a[2]), "r"(a[3]), "r"(b[0]), "r"(b[1]));
}

// ---------------------------------------------------------------------------
// Kernel 1: fold constants -> tf32 operator, stored as frag-pair image:
//   g_Apair[kt][n][tg] = ( A[kt*8+tg][n], A[kt*8+tg+4][n] )   (float2)
// A_op[n,d] = ( sum_m Wre[n,m]*ReJ[m,d] - Wim[n,m]*ImJ[m,d] ) / 101
// ---------------------------------------------------------------------------
extern __shared__ float bsm[];
__global__ void build_A_kernel(const float* __restrict__ Wre,
                               const float* __restrict__ Wim,
                               const float* __restrict__ ReJ,
                               const float* __restrict__ ImJ) {
    float* sRe = bsm;
    float* sIm = bsm + 10201;
    float* sW  = bsm + 20402;          // [Wre row][Wim row]
    const int tid = threadIdx.x;       // 128
    const int n   = blockIdx.x;        // 0..103

    for (int i = tid; i < 10201; i += 128) { sRe[i] = ReJ[i]; sIm[i] = ImJ[i]; }
    for (int i = tid; i < DD; i += 128) {
        sW[i]      = (n < KO) ? Wre[n * DD + i] : 0.0f;
        sW[DD + i] = (n < KO) ? Wim[n * DD + i] : 0.0f;
    }
    __syncthreads();

    const int d = tid;                 // k index
    if (d >= KPAD) return;
    float a = 0.0f;
    if (n < KO && d < DD) {
        float a0 = 0.f, a1 = 0.f;
        #pragma unroll 1
        for (int m = 0; m + 2 <= DD; m += 2) {
            a0 = fmaf(sW[m],        sRe[m*DD+d],     a0);
            a0 = fmaf(-sW[DD+m],    sIm[m*DD+d],     a0);
            a1 = fmaf(sW[m+1],      sRe[(m+1)*DD+d], a1);
            a1 = fmaf(-sW[DD+m+1],  sIm[(m+1)*DD+d], a1);
        }
        a0 = fmaf(sW[DD-1],     sRe[(DD-1)*DD+d], a0);
        a0 = fmaf(-sW[2*DD-1],  sIm[(DD-1)*DD+d], a0);
        a = (a0 + a1) * (1.0f / 101.0f);
    }
    const int kt   = d >> 3;
    const int r    = d & 7;
    const int tg   = r & 3;
    const int slot = r >> 2;           // 0: k0+tg, 1: k0+tg+4
    *(uint32_t*)(g_Apair + kt * 3328 + n * 32 + tg * 8 + slot * 4) = to_tf32(a);
}

// ---------------------------------------------------------------------------
// Kernel 2: persistent tf32 GEMM; paired-B LDS.64; smem-staged TMA epilogue.
// ---------------------------------------------------------------------------
extern __shared__ unsigned char smem[];

__global__ void __launch_bounds__(NTHR, 2)
fourier_mma_kernel(const float* __restrict__ x, float* __restrict__ out,
                   int ntiles) {
    const int tid   = threadIdx.x;
    const int wid   = tid >> 5;
    const int lane  = tid & 31;
    const int g     = lane >> 2;
    const int tg    = lane & 3;
    const int mwarp = wid >> 1;
    const int nhalf = wid & 1;
    const int NT    = nhalf ? 6 : 7;
    const uint32_t sbase = smem_u32(smem);
    const uint32_t mb0 = sbase + MBAR_OFF;
    const uint32_t mb1 = sbase + MBAR_OFF + 8;

    // zero raw pad tails (K-tail overreads must be finite)
    for (int i = tid; i < (RAW_SLOT - TILE_BYTES) / 4; i += NTHR) {
        *(uint32_t*)(smem + RAW0_OFF + TILE_BYTES + i * 4) = 0;
        *(uint32_t*)(smem + RAW1_OFF + TILE_BYTES + i * 4) = 0;
    }
    if (tid == 0) { mbar_init(mb0, 1); mbar_init(mb1, 1); }
    __syncthreads();

    int t = blockIdx.x;
    if (tid == 0) {
        mbar_expect_tx(mb0, A_IMG_BYTES + TILE_BYTES);
        bulk_g2s(sbase + AIMG_OFF, g_Apair, A_IMG_BYTES, mb0);
        bulk_g2s(sbase + RAW0_OFF, (const char*)x + (size_t)t * TILE_BYTES,
                 TILE_BYTES, mb0);
    }

    // a-frag base: row = mwarp*16 + g, k word = tg
    const uint32_t ra = (uint32_t)((mwarp * 16 + g) * DD + tg) * 4u;
    // b pair base: [kt=0][n = nhalf*56 + g][tg]
    const uint32_t rbA = sbase + AIMG_OFF
        + (uint32_t)((nhalf * 56 + g) * 32 + tg * 8);

    int buf = 0;
    uint32_t par0 = 0, par1 = 0;
    #pragma unroll 1
    for (; t < ntiles; t += GRID) {
        const int tn = t + GRID;
        if (tn < ntiles && tid == 0) {
            // the target buffer was the S2G source two phases ago — drain stores
            S2G_WAIT0();
            const uint32_t mb_nxt = buf ? mb0 : mb1;
            mbar_expect_tx(mb_nxt, TILE_BYTES);
            bulk_g2s(sbase + (buf ? RAW0_OFF : RAW1_OFF),
                     (const char*)x + (size_t)tn * TILE_BYTES, TILE_BYTES, mb_nxt);
        }
        if (buf) { mbar_wait(mb1, par1); par1 ^= 1; }
        else     { mbar_wait(mb0, par0); par0 ^= 1; }

        float acc[7][4];
        #pragma unroll
        for (int nt = 0; nt < 7; ++nt)
            #pragma unroll
            for (int i = 0; i < 4; ++i) acc[nt][i] = 0.0f;

        const uint32_t rawb = sbase + (buf ? RAW1_OFF : RAW0_OFF);
        const uint32_t rx = rawb + ra;

        #pragma unroll
        for (int kt = 0; kt < 13; ++kt) {
            // a-frag: x rows (r0, r0+8), k cols (k0+tg, k0+tg+4)
            const uint32_t ka = rx + (uint32_t)kt * 32u;
            uint32_t a[4];
            a[0] = to_tf32(ldsf(ka));
            a[1] = to_tf32(ldsf(ka + 3232));        // +8 rows (8*101*4)
            a[2] = to_tf32(ldsf(ka + 16));          // +4 k cols
            a[3] = to_tf32(ldsf(ka + 3232 + 16));

            // b-frags: one LDS.64 per n-tile
            const uint32_t kb = rbA + (uint32_t)kt * 3328u;
            uint32_t b[7][2];
            #pragma unroll
            for (int nt = 0; nt < 7; ++nt)
                if (nt < NT) ldsv2(b[nt], kb + (uint32_t)nt * 256u);
            #pragma unroll
            for (int nt = 0; nt < 7; ++nt)
                if (nt < NT) mma_tf32(acc[nt], a, b[nt]);
        }

        // ---- epilogue: stage exact [64 x 101] fp32 image into raw[buf] ----
        __syncthreads();   // nhalf partner may still read this row-block's x
        {
            const uint32_t st0 = rawb + (uint32_t)((mwarp * 16 + g) * KO) * 4u;
            #pragma unroll
            for (int nt = 0; nt < 7; ++nt) {
                if (nt >= NT) break;
                const int col = nhalf * 56 + nt * 8 + tg * 2;
                if (col < KO) {
                    stsf(st0 + (uint32_t)col * 4u, acc[nt][0]);
                    stsf(st0 + (uint32_t)(8 * KO + col) * 4u, acc[nt][2]);
                    if (col + 1 < KO) {
                        stsf(st0 + (uint32_t)(col + 1) * 4u, acc[nt][1]);
                        stsf(st0 + (uint32_t)(8 * KO + col + 1) * 4u, acc[nt][3]);
                    }
                }
            }
        }
        __syncthreads();   // full tile staged
        if (tid == 0) {
            asm volatile("fence.proxy.async.shared::cta;" ::: "memory");
            bulk_s2g(out + (size_t)t * (BM * KO), rawb, TILE_BYTES);
            S2G_COMMIT();
        }
        buf ^= 1;
    }
    if (tid == 0) S2G_WAIT0();   // drain last store before exit
}

// ---------------------------------------------------------------------------
// Launch
// ---------------------------------------------------------------------------
extern "C" void kernel_launch(void* const* d_in, const int* in_sizes, int n_in,
                              void* d_out, int out_size) {
    const float* x   = (const float*)d_in[0];
    const float* Wre = (const float*)d_in[1];
    const float* Wim = (const float*)d_in[2];
    const float* ReJ = (const float*)d_in[3];
    const float* ImJ = (const float*)d_in[4];
    float* out = (float*)d_out;

    const int B = in_sizes[0] / DD;       // 262144
    const int ntiles = B / BM;            // 4096

    const int build_smem = (20402 + 2 * DD) * (int)sizeof(float);
    cudaFuncSetAttribute(build_A_kernel,
                         cudaFuncAttributeMaxDynamicSharedMemorySize, build_smem);
    build_A_kernel<<<KPAD, 128, build_smem>>>(Wre, Wim, ReJ, ImJ);

    cudaFuncSetAttribute(fourier_mma_kernel,
                         cudaFuncAttributeMaxDynamicSharedMemorySize, SMEM_BYTES);
    fourier_mma_kernel<<<GRID, NTHR, SMEM_BYTES>>>(x, out, ntiles);
    (void)n_in; (void)out_size;
}

// round 9
// speedup vs baseline: 1.7365x; 1.1333x over previous
#include <cuda_runtime.h>
#include <cuda_bf16.h>
#include <cstdint>

// ---------------------------------------------------------------------------
// Problem constants
// ---------------------------------------------------------------------------
#define DD    101                 // inner dim
#define KO    101                 // output cols
#define KPAD  104                 // 13 * 8
#define BM    64                  // batch rows per tile
#define NTHR  128                 // 4 warps: 2 mwarps (M=32) x 2 nhalf

// B image: [kt][n][tg] float2 pairs = (A[k0+tg][n], A[k0+tg+4][n])
#define A_IMG_BYTES (13 * KPAD * 4 * 8)   // 43264

#define TILE_BYTES (BM * DD * 4)          // 25856
#define RAW_SLOT   26112                  // tile + 256 zeroed pad

// smem layout (bytes)
#define RAW0_OFF 0
#define RAW1_OFF RAW_SLOT                 // 26112
#define AIMG_OFF (2 * RAW_SLOT)           // 52224
#define MBAR_OFF (AIMG_OFF + A_IMG_BYTES) // 95488
#define SMEM_BYTES 95552

#define GRID 296                          // 2 CTAs/SM

__device__ __align__(16) unsigned char g_Apair[A_IMG_BYTES];

// ---------------------------------------------------------------------------
// Helpers
// ---------------------------------------------------------------------------
__device__ __forceinline__ uint32_t smem_u32(const void* p) {
    uint32_t a;
    asm("{ .reg .u64 t; cvta.to.shared.u64 t, %1; cvt.u32.u64 %0, t; }"
        : "=r"(a) : "l"(p));
    return a;
}
__device__ __forceinline__ void mbar_init(uint32_t m, uint32_t cnt) {
    asm volatile("mbarrier.init.shared.b64 [%0], %1;" :: "r"(m), "r"(cnt) : "memory");
}
__device__ __forceinline__ void mbar_expect_tx(uint32_t m, uint32_t bytes) {
    asm volatile("mbarrier.arrive.expect_tx.shared.b64 _, [%0], %1;"
                 :: "r"(m), "r"(bytes) : "memory");
}
__device__ __forceinline__ void mbar_wait(uint32_t m, uint32_t parity) {
    asm volatile(
        "{\n\t.reg .pred P;\n"
        "W_%=:\n\t"
        "mbarrier.try_wait.parity.acquire.cta.shared::cta.b64 P, [%0], %1;\n\t"
        "@!P bra W_%=;\n\t}"
        :: "r"(m), "r"(parity) : "memory");
}
__device__ __forceinline__ void bulk_g2s(uint32_t dst, const void* src,
                                         uint32_t bytes, uint32_t m) {
    asm volatile(
        "cp.async.bulk.shared::cta.global.mbarrier::complete_tx::bytes "
        "[%0], [%1], %2, [%3];"
        :: "r"(dst), "l"(src), "r"(bytes), "r"(m) : "memory");
}
__device__ __forceinline__ void bulk_s2g(void* gdst, uint32_t ssrc, uint32_t bytes) {
    asm volatile("cp.async.bulk.global.shared::cta.bulk_group [%0], [%1], %2;"
                 :: "l"(gdst), "r"(ssrc), "r"(bytes) : "memory");
}
#define S2G_COMMIT() asm volatile("cp.async.bulk.commit_group;" ::: "memory")
#define S2G_WAIT0()  asm volatile("cp.async.bulk.wait_group 0;" ::: "memory")

__device__ __forceinline__ float ldsf(uint32_t a) {
    float v;
    asm volatile("ld.shared.f32 %0, [%1];" : "=f"(v) : "r"(a));
    return v;
}
__device__ __forceinline__ void ldsv2(uint32_t* r, uint32_t a) {
    asm volatile("ld.shared.v2.b32 {%0,%1}, [%2];"
                 : "=r"(r[0]), "=r"(r[1]) : "r"(a));
}
__device__ __forceinline__ void stsf(uint32_t a, float v) {
    asm volatile("st.shared.f32 [%0], %1;" :: "r"(a), "f"(v) : "memory");
}
__device__ __forceinline__ uint32_t to_tf32(float f) {
    uint32_t r;
    asm("cvt.rna.tf32.f32 %0, %1;" : "=r"(r) : "f"(f));
    return r;
}
__device__ __forceinline__ void mma_tf32(float* c, const uint32_t* a,
                                         const uint32_t* b) {
    asm volatile(
        "mma.sync.aligned.m16n8k8.row.col.f32.tf32.tf32.f32 "
        "{%0,%1,%2,%3}, {%4,%5,%6,%7}, {%8,%9}, {%0,%1,%2,%3};"
        : "+f"(c[0]), "+f"(c[1]), "+f"(c[2]), "+f"(c[3])
        : "r"(a[0]), "r"(a[1]), "r"(a[2]), "r"(a[3]), "r"(b[0]), "r"(b[1]));
}

// ---------------------------------------------------------------------------
// Kernel 1: fold constants -> tf32 operator, stored as frag-pair image:
//   g_Apair[kt][n][tg] = ( A[kt*8+tg][n], A[kt*8+tg+4][n] )   (float2)
// A_op[n,d] = ( sum_m Wre[n,m]*ReJ[m,d] - Wim[n,m]*ImJ[m,d] ) / 101
// ---------------------------------------------------------------------------
extern __shared__ float bsm[];
__global__ void build_A_kernel(const float* __restrict__ Wre,
                               const float* __restrict__ Wim,
                               const float* __restrict__ ReJ,
                               const float* __restrict__ ImJ) {
    float* sRe = bsm;
    float* sIm = bsm + 10201;
    float* sW  = bsm + 20402;          // [Wre row][Wim row]
    const int tid = threadIdx.x;       // 128
    const int n   = blockIdx.x;        // 0..103

    for (int i = tid; i < 10201; i += 128) { sRe[i] = ReJ[i]; sIm[i] = ImJ[i]; }
    for (int i = tid; i < DD; i += 128) {
        sW[i]      = (n < KO) ? Wre[n * DD + i] : 0.0f;
        sW[DD + i] = (n < KO) ? Wim[n * DD + i] : 0.0f;
    }
    __syncthreads();

    const int d = tid;                 // k index
    if (d >= KPAD) return;
    float a = 0.0f;
    if (n < KO && d < DD) {
        float a0 = 0.f, a1 = 0.f;
        #pragma unroll 1
        for (int m = 0; m + 2 <= DD; m += 2) {
            a0 = fmaf(sW[m],        sRe[m*DD+d],     a0);
            a0 = fmaf(-sW[DD+m],    sIm[m*DD+d],     a0);
            a1 = fmaf(sW[m+1],      sRe[(m+1)*DD+d], a1);
            a1 = fmaf(-sW[DD+m+1],  sIm[(m+1)*DD+d], a1);
        }
        a0 = fmaf(sW[DD-1],     sRe[(DD-1)*DD+d], a0);
        a0 = fmaf(-sW[2*DD-1],  sIm[(DD-1)*DD+d], a0);
        a = (a0 + a1) * (1.0f / 101.0f);
    }
    const int kt   = d >> 3;
    const int r    = d & 7;
    const int tg   = r & 3;
    const int slot = r >> 2;           // 0: k0+tg, 1: k0+tg+4
    *(uint32_t*)(g_Apair + kt * 3328 + n * 32 + tg * 8 + slot * 4) = to_tf32(a);
}

// ---------------------------------------------------------------------------
// Kernel 2: persistent tf32 GEMM. Warp tile M=32 (2 m-frags) halves B smem
// traffic; physical rows are permuted (class mod 4) so all a-frag scalar LDS
// are bank-conflict-free:
//   warp m, frag f, group g -> physical rows (2m+f+4g) and (2m+f+4g+32).
// ---------------------------------------------------------------------------
extern __shared__ unsigned char smem[];

__global__ void __launch_bounds__(NTHR, 2)
fourier_mma_kernel(const float* __restrict__ x, float* __restrict__ out,
                   int ntiles) {
    const int tid   = threadIdx.x;
    const int wid   = tid >> 5;       // 0..3
    const int lane  = tid & 31;
    const int g     = lane >> 2;
    const int tg    = lane & 3;
    const int mwarp = wid >> 1;       // 0..1, row classes {2m, 2m+1}
    const int nhalf = wid & 1;
    const int NT    = nhalf ? 6 : 7;
    const uint32_t sbase = smem_u32(smem);
    const uint32_t mb0 = sbase + MBAR_OFF;
    const uint32_t mb1 = sbase + MBAR_OFF + 8;

    // zero raw pad tails (K-tail overreads must be finite)
    for (int i = tid; i < (RAW_SLOT - TILE_BYTES) / 4; i += NTHR) {
        *(uint32_t*)(smem + RAW0_OFF + TILE_BYTES + i * 4) = 0;
        *(uint32_t*)(smem + RAW1_OFF + TILE_BYTES + i * 4) = 0;
    }
    if (tid == 0) { mbar_init(mb0, 1); mbar_init(mb1, 1); }
    __syncthreads();

    int t = blockIdx.x;
    if (tid == 0) {
        mbar_expect_tx(mb0, A_IMG_BYTES + TILE_BYTES);
        bulk_g2s(sbase + AIMG_OFF, g_Apair, A_IMG_BYTES, mb0);
        bulk_g2s(sbase + RAW0_OFF, (const char*)x + (size_t)t * TILE_BYTES,
                 TILE_BYTES, mb0);
    }

    // a-frag bases: frag f, row = (2m+f) + 4g, k word = tg
    //   conflict-free: banks (row*101+tg) mod 32 bijective for rows = c+4g.
    const uint32_t ra0 = (uint32_t)(((2 * mwarp + 0) + 4 * g) * DD + tg) * 4u;
    const uint32_t ra1 = (uint32_t)(((2 * mwarp + 1) + 4 * g) * DD + tg) * 4u;
    // b pair base: [kt=0][n = nhalf*56 + g][tg]
    const uint32_t rbA = sbase + AIMG_OFF
        + (uint32_t)((nhalf * 56 + g) * 32 + tg * 8);

    int buf = 0;
    uint32_t par0 = 0, par1 = 0;
    #pragma unroll 1
    for (; t < ntiles; t += GRID) {
        const int tn = t + GRID;
        if (tn < ntiles && tid == 0) {
            S2G_WAIT0();      // target buffer was S2G source two phases ago
            const uint32_t mb_nxt = buf ? mb0 : mb1;
            mbar_expect_tx(mb_nxt, TILE_BYTES);
            bulk_g2s(sbase + (buf ? RAW0_OFF : RAW1_OFF),
                     (const char*)x + (size_t)tn * TILE_BYTES, TILE_BYTES, mb_nxt);
        }
        if (buf) { mbar_wait(mb1, par1); par1 ^= 1; }
        else     { mbar_wait(mb0, par0); par0 ^= 1; }

        float acc[2][7][4];
        #pragma unroll
        for (int f = 0; f < 2; ++f)
            #pragma unroll
            for (int nt = 0; nt < 7; ++nt)
                #pragma unroll
                for (int i = 0; i < 4; ++i) acc[f][nt][i] = 0.0f;

        const uint32_t rawb = sbase + (buf ? RAW1_OFF : RAW0_OFF);
        const uint32_t rx0 = rawb + ra0;
        const uint32_t rx1 = rawb + ra1;

        #pragma unroll
        for (int kt = 0; kt < 13; ++kt) {
            const uint32_t ko = (uint32_t)kt * 32u;
            // a-frags: +12928 = 32 rows; +16 = k+4 cols
            uint32_t a0[4], a1[4];
            a0[0] = to_tf32(ldsf(rx0 + ko));
            a0[1] = to_tf32(ldsf(rx0 + ko + 12928));
            a0[2] = to_tf32(ldsf(rx0 + ko + 16));
            a0[3] = to_tf32(ldsf(rx0 + ko + 12928 + 16));
            a1[0] = to_tf32(ldsf(rx1 + ko));
            a1[1] = to_tf32(ldsf(rx1 + ko + 12928));
            a1[2] = to_tf32(ldsf(rx1 + ko + 16));
            a1[3] = to_tf32(ldsf(rx1 + ko + 12928 + 16));

            // b-frags: one LDS.64 per n-tile (conflict-free per 16-lane phase)
            const uint32_t kb = rbA + (uint32_t)kt * 3328u;
            uint32_t b[7][2];
            #pragma unroll
            for (int nt = 0; nt < 7; ++nt)
                if (nt < NT) ldsv2(b[nt], kb + (uint32_t)nt * 256u);

            // term-grouped: 13-14 independent acc chains
            #pragma unroll
            for (int nt = 0; nt < 7; ++nt)
                if (nt < NT) mma_tf32(acc[0][nt], a0, b[nt]);
            #pragma unroll
            for (int nt = 0; nt < 7; ++nt)
                if (nt < NT) mma_tf32(acc[1][nt], a1, b[nt]);
        }

        // ---- epilogue: stage exact [64 x 101] fp32 image into raw[buf] ----
        __syncthreads();   // other warps may still read this buffer's x
        {
            #pragma unroll
            for (int f = 0; f < 2; ++f) {
                // physical rows: (2m+f+4g) and +32; staged rows are 101 words
                const uint32_t st0 = rawb
                    + (uint32_t)(((2 * mwarp + f) + 4 * g) * KO) * 4u;
                #pragma unroll
                for (int nt = 0; nt < 7; ++nt) {
                    if (nt >= NT) break;
                    const int col = nhalf * 56 + nt * 8 + tg * 2;
                    if (col < KO) {
                        stsf(st0 + (uint32_t)col * 4u, acc[f][nt][0]);
                        stsf(st0 + 12928u + (uint32_t)col * 4u, acc[f][nt][2]);
                        if (col + 1 < KO) {
                            stsf(st0 + (uint32_t)(col + 1) * 4u, acc[f][nt][1]);
                            stsf(st0 + 12928u + (uint32_t)(col + 1) * 4u,
                                 acc[f][nt][3]);
                        }
                    }
                }
            }
        }
        __syncthreads();   // full tile staged
        if (tid == 0) {
            asm volatile("fence.proxy.async.shared::cta;" ::: "memory");
            bulk_s2g(out + (size_t)t * (BM * KO), rawb, TILE_BYTES);
            S2G_COMMIT();
        }
        buf ^= 1;
    }
    if (tid == 0) S2G_WAIT0();
}

// ---------------------------------------------------------------------------
// Launch
// ---------------------------------------------------------------------------
extern "C" void kernel_launch(void* const* d_in, const int* in_sizes, int n_in,
                              void* d_out, int out_size) {
    const float* x   = (const float*)d_in[0];
    const float* Wre = (const float*)d_in[1];
    const float* Wim = (const float*)d_in[2];
    const float* ReJ = (const float*)d_in[3];
    const float* ImJ = (const float*)d_in[4];
    float* out = (float*)d_out;

    const int B = in_sizes[0] / DD;       // 262144
    const int ntiles = B / BM;            // 4096

    const int build_smem = (20402 + 2 * DD) * (int)sizeof(float);
    cudaFuncSetAttribute(build_A_kernel,
                         cudaFuncAttributeMaxDynamicSharedMemorySize, build_smem);
    build_A_kernel<<<KPAD, 128, build_smem>>>(Wre, Wim, ReJ, ImJ);

    cudaFuncSetAttribute(fourier_mma_kernel,
                         cudaFuncAttributeMaxDynamicSharedMemorySize, SMEM_BYTES);
    fourier_mma_kernel<<<GRID, NTHR, SMEM_BYTES>>>(x, out, ntiles);
    (void)n_in; (void)out_size;
}